// round 2
// baseline (speedup 1.0000x reference)
#include <cuda_runtime.h>
#include <cstdint>

// Problem constants (fixed by dataset shapes)
#define BATCH 4
#define NV    4096
#define NC    128
#define NS    1024   // NV / POOLING_RATE
#define KNBR  4

// -------- device scratch (no allocation allowed) --------
__device__ __align__(16) int g_rank[2][NV];
__device__ int g_sample[NS];
__device__ __align__(16) int g_nbr[BATCH * NS * KNBR];

// -------- JAX threefry2x32 (20 rounds), host+device --------
__host__ __device__ __forceinline__ void threefry2x32(
    uint32_t k0, uint32_t k1, uint32_t x0, uint32_t x1,
    uint32_t* o0, uint32_t* o1)
{
    uint32_t ks2 = k0 ^ k1 ^ 0x1BD11BDAu;
    x0 += k0; x1 += k1;
#define TF_ROT(x, r) (((x) << (r)) | ((x) >> (32 - (r))))
#define TF_R4(a, b, c, d)                       \
    x0 += x1; x1 = TF_ROT(x1, a); x1 ^= x0;     \
    x0 += x1; x1 = TF_ROT(x1, b); x1 ^= x0;     \
    x0 += x1; x1 = TF_ROT(x1, c); x1 ^= x0;     \
    x0 += x1; x1 = TF_ROT(x1, d); x1 ^= x0;
    TF_R4(13, 15, 26, 6);  x0 += k1;  x1 += ks2 + 1u;
    TF_R4(17, 29, 16, 24); x0 += ks2; x1 += k0 + 2u;
    TF_R4(13, 15, 26, 6);  x0 += k0;  x1 += k1 + 3u;
    TF_R4(17, 29, 16, 24); x0 += k1;  x1 += ks2 + 4u;
    TF_R4(13, 15, 26, 6);  x0 += ks2; x1 += k0 + 5u;
#undef TF_R4
#undef TF_ROT
    *o0 = x0; *o1 = x1;
}

// -------- K_rank: partitionable-threefry sort keys + stable rank -----------
// Partitionable random_bits(32): sk[i] = w0 ^ w1 of cipher(subkey; 0, i).
// grid = 256 blocks (round = bx>>7, 32 elements per block), block = 256
__global__ void rank_kernel(uint32_t s10, uint32_t s11, uint32_t s20, uint32_t s21)
{
    __shared__ __align__(16) uint32_t sk[NV];
    int r = blockIdx.x >> 7;
    uint32_t sub0 = r ? s20 : s10;
    uint32_t sub1 = r ? s21 : s11;

    for (int p = threadIdx.x; p < NV; p += blockDim.x) {
        uint32_t w0, w1;
        threefry2x32(sub0, sub1, 0u, (uint32_t)p, &w0, &w1);
        sk[p] = w0 ^ w1;
    }
    __syncthreads();

    // 8 scanner-threads per element, 512 keys each, uint4 loads
    int elem = ((blockIdx.x & 127) << 5) + (threadIdx.x >> 3);
    int seg  = threadIdx.x & 7;
    uint32_t mk = sk[elem];
    int cnt = 0;
    const uint4* sk4 = (const uint4*)sk;
    int base4 = seg * (NV / 8 / 4);  // 128 uint4 per segment
#pragma unroll 4
    for (int u = 0; u < NV / 8 / 4; ++u) {
        uint4 kk = sk4[base4 + u];
        int j = (base4 + u) * 4;
        cnt += (kk.x < mk) || (kk.x == mk && (j + 0) < elem);
        cnt += (kk.y < mk) || (kk.y == mk && (j + 1) < elem);
        cnt += (kk.z < mk) || (kk.z == mk && (j + 2) < elem);
        cnt += (kk.w < mk) || (kk.w == mk && (j + 3) < elem);
    }
    cnt += __shfl_down_sync(0xffffffffu, cnt, 4, 8);
    cnt += __shfl_down_sync(0xffffffffu, cnt, 2, 8);
    cnt += __shfl_down_sync(0xffffffffu, cnt, 1, 8);
    if (seg == 0) g_rank[r][elem] = cnt;
}

// -------- K_compose: sample_idx[rank2[rank1[i]]] = i (keep first 1024) -----
__global__ void compose_kernel()
{
    int i = blockIdx.x * blockDim.x + threadIdx.x;
    if (i < NV) {
        int pos = g_rank[1][g_rank[0][i]];
        if (pos < NS) g_sample[pos] = i;
    }
}

// -------- K_knn: warp-per-sampled-query top-4 neighbors ---------------------
// grid = BATCH*128 = 512 blocks, block = 256 (8 warps => 8 queries)
__global__ void knn_kernel(const float* __restrict__ Vtx)
{
    __shared__ float sx[NV], sy[NV], sz[NV];  // 48KB
    int b = blockIdx.x >> 7;
    const float* vb = Vtx + b * NV * 3;
    for (int idx = threadIdx.x; idx < NV * 3; idx += blockDim.x) {
        float v = vb[idx];
        int m = idx / 3, d = idx - 3 * m;
        if (d == 0) sx[m] = v;
        else if (d == 1) sy[m] = v;
        else sz[m] = v;
    }
    __syncthreads();

    int warp = threadIdx.x >> 5;
    int lane = threadIdx.x & 31;
    int s = ((blockIdx.x & 127) << 3) + warp;
    int n = g_sample[s];
    float xn = sx[n], yn = sy[n], zn = sz[n];
    float qn = xn * xn + yn * yn + zn * zn;

    // per-lane sorted top-4 of packed (dist_bits<<32 | idx)
    unsigned long long k0 = ~0ULL, k1 = ~0ULL, k2 = ~0ULL, k3 = ~0ULL;
    for (int m = lane; m < NV; m += 32) {
        float xm = sx[m], ym = sy[m], zm = sz[m];
        float qm = xm * xm + ym * ym + zm * zm;
        float inner = xn * xm + yn * ym + zn * zm;
        float d = (-2.0f * inner + qm) + qn;   // matches reference assoc
        unsigned long long key =
            ((unsigned long long)__float_as_uint(d) << 32) | (unsigned)m;
        if (m == n) key = ~0ULL;  // exclude self
        if (key < k3) {
            if (key < k2) {
                k3 = k2;
                if (key < k1) {
                    k2 = k1;
                    if (key < k0) { k1 = k0; k0 = key; } else k1 = key;
                } else k2 = key;
            } else k3 = key;
        }
    }

    // warp merge: pop global min 4 times (indices make keys unique)
    int res[4];
#pragma unroll
    for (int t = 0; t < 4; ++t) {
        unsigned long long mn = k0;
#pragma unroll
        for (int off = 16; off; off >>= 1) {
            unsigned long long o = __shfl_xor_sync(0xffffffffu, mn, off);
            mn = (o < mn) ? o : mn;
        }
        if (k0 == mn) { k0 = k1; k1 = k2; k2 = k3; k3 = ~0ULL; }
        res[t] = (int)(unsigned)(mn & 0xffffffffULL);
    }
    if (lane == 0) {
        int4 w = make_int4(res[0], res[1], res[2], res[3]);
        *(int4*)&g_nbr[(b * NS + s) * KNBR] = w;
    }
}

// -------- K_pool: plane-per-block max-pool gather + vertices_pool -----------
// grid = BATCH*NC = 512 blocks, block = 256
__global__ void pool_kernel(const float* __restrict__ F,
                            const float* __restrict__ Vtx,
                            float* __restrict__ out)
{
    __shared__ __align__(16) float sf[NV * 3];  // 48KB plane
    int b = blockIdx.x >> 7;
    int c = blockIdx.x & 127;
    const float4* p4 = (const float4*)(F + (size_t)(b * NC + c) * NV * 3);
    float4* s4 = (float4*)sf;
#pragma unroll 4
    for (int i = threadIdx.x; i < NV * 3 / 4; i += blockDim.x) s4[i] = p4[i];
    __syncthreads();

    float* fout = out + BATCH * NS * 3;  // feature_map_pool region
    for (int t = threadIdx.x; t < NS; t += blockDim.x) {
        int4 nb = *(const int4*)&g_nbr[(b * NS + t) * KNBR];
        int j0 = nb.x * 3, j1 = nb.y * 3, j2 = nb.z * 3, j3 = nb.w * 3;
        float o0 = fmaxf(fmaxf(sf[j0],     sf[j1]),     fmaxf(sf[j2],     sf[j3]));
        float o1 = fmaxf(fmaxf(sf[j0 + 1], sf[j1 + 1]), fmaxf(sf[j2 + 1], sf[j3 + 1]));
        float o2 = fmaxf(fmaxf(sf[j0 + 2], sf[j1 + 2]), fmaxf(sf[j2 + 2], sf[j3 + 2]));
        size_t ob = ((size_t)(b * NC + c) * NS + t) * 3;
        fout[ob] = o0; fout[ob + 1] = o1; fout[ob + 2] = o2;
    }

    // c==0 blocks also emit vertices_pool (b,1024,3)
    if (c == 0) {
        const float* vb = Vtx + b * NV * 3;
        for (int t = threadIdx.x; t < NS * 3; t += blockDim.x) {
            int s = t / 3, d = t - 3 * s;
            out[(b * NS + s) * 3 + d] = vb[g_sample[s] * 3 + d];
        }
    }
}

// -------- host entry --------
extern "C" void kernel_launch(void* const* d_in, const int* in_sizes, int n_in,
                              void* d_out, int out_size)
{
    const float* Vtx;
    const float* F;
    if (in_sizes[0] == BATCH * NV * 3) {
        Vtx = (const float*)d_in[0];
        F   = (const float*)d_in[1];
    } else {
        Vtx = (const float*)d_in[1];
        F   = (const float*)d_in[0];
    }

    // Replicate jax.random.key(42) + two *partitionable/foldlike* splits on the
    // host. foldlike split(key, (2,)): keys[i] = cipher(key; hi=0, lo=i).
    //   key_new = cipher(k; 0,0), subkey = cipher(k; 0,1)  (both output words)
    uint32_t k10, k11, sub1_0, sub1_1, sub2_0, sub2_1, t0, t1;
    threefry2x32(0u, 42u, 0u, 0u, &k10, &k11);      // round-1 carry key
    threefry2x32(0u, 42u, 0u, 1u, &sub1_0, &sub1_1); // round-1 subkey
    threefry2x32(k10, k11, 0u, 0u, &t0, &t1);        // round-2 carry key (unused)
    threefry2x32(k10, k11, 0u, 1u, &sub2_0, &sub2_1);// round-2 subkey
    (void)t0; (void)t1;

    rank_kernel<<<256, 256>>>(sub1_0, sub1_1, sub2_0, sub2_1);
    compose_kernel<<<16, 256>>>();
    knn_kernel<<<BATCH * 128, 256>>>(Vtx);
    pool_kernel<<<BATCH * NC, 256>>>(F, Vtx, (float*)d_out);
}

// round 3
// speedup vs baseline: 1.6430x; 1.6430x over previous
#include <cuda_runtime.h>
#include <cstdint>
#include <algorithm>

// Problem constants (fixed by dataset shapes)
#define BATCH 4
#define NV    4096
#define NC    128
#define NS    1024   // NV / POOLING_RATE
#define KNBR  4
#define PLF   (NV * 3)   // floats per (b,c) feature plane = 12288

struct Samp { int s[NS]; };   // 4KB by-value kernel parameter

// -------- device scratch (no allocation allowed) --------
__device__ __align__(16) int g_nbr[BATCH * NS * KNBR];

// -------- JAX threefry2x32 (20 rounds), host-usable --------
__host__ __device__ __forceinline__ void threefry2x32(
    uint32_t k0, uint32_t k1, uint32_t x0, uint32_t x1,
    uint32_t* o0, uint32_t* o1)
{
    uint32_t ks2 = k0 ^ k1 ^ 0x1BD11BDAu;
    x0 += k0; x1 += k1;
#define TF_ROT(x, r) (((x) << (r)) | ((x) >> (32 - (r))))
#define TF_R4(a, b, c, d)                       \
    x0 += x1; x1 = TF_ROT(x1, a); x1 ^= x0;     \
    x0 += x1; x1 = TF_ROT(x1, b); x1 ^= x0;     \
    x0 += x1; x1 = TF_ROT(x1, c); x1 ^= x0;     \
    x0 += x1; x1 = TF_ROT(x1, d); x1 ^= x0;
    TF_R4(13, 15, 26, 6);  x0 += k1;  x1 += ks2 + 1u;
    TF_R4(17, 29, 16, 24); x0 += ks2; x1 += k0 + 2u;
    TF_R4(13, 15, 26, 6);  x0 += k0;  x1 += k1 + 3u;
    TF_R4(17, 29, 16, 24); x0 += k1;  x1 += ks2 + 4u;
    TF_R4(13, 15, 26, 6);  x0 += ks2; x1 += k0 + 5u;
#undef TF_R4
#undef TF_ROT
    *o0 = x0; *o1 = x1;
}

// -------- K_knn: 2 warps per query, top-4 neighbors ------------------------
// grid = BATCH*128 = 512 blocks, block = 512 (16 warps = 8 queries x 2 halves)
__global__ __launch_bounds__(512) void knn_kernel(const float* __restrict__ Vtx,
                                                  Samp smp)
{
    __shared__ float sx[NV], sy[NV], sz[NV];  // 48KB
    int b = blockIdx.x >> 7;
    const float* vb = Vtx + b * NV * 3;
    for (int idx = threadIdx.x; idx < NV * 3; idx += 512) {
        float v = vb[idx];
        int m = idx / 3, d = idx - 3 * m;
        if (d == 0) sx[m] = v;
        else if (d == 1) sy[m] = v;
        else sz[m] = v;
    }
    __syncthreads();

    int warp = threadIdx.x >> 5;
    int lane = threadIdx.x & 31;
    int q = warp >> 1;        // query slot within block (0..7)
    int half = warp & 1;      // which half of the 4096 points this warp scans
    int s = ((blockIdx.x & 127) << 3) + q;
    int n = smp.s[s];
    float xn = sx[n], yn = sy[n], zn = sz[n];
    float qn = xn * xn + yn * yn + zn * zn;

    // per-lane sorted top-4 of packed (dist_bits<<32 | idx) over this half
    unsigned long long k0 = ~0ULL, k1 = ~0ULL, k2 = ~0ULL, k3 = ~0ULL;
    int mend = half * 2048 + 2048;
    for (int m = half * 2048 + lane; m < mend; m += 32) {
        float xm = sx[m], ym = sy[m], zm = sz[m];
        float qm = xm * xm + ym * ym + zm * zm;
        float inner = xn * xm + yn * ym + zn * zm;
        float d = (-2.0f * inner + qm) + qn;   // matches reference assoc
        unsigned long long key =
            ((unsigned long long)__float_as_uint(d) << 32) | (unsigned)m;
        if (m == n) key = ~0ULL;  // exclude self
        if (key < k3) {
            if (key < k2) {
                k3 = k2;
                if (key < k1) {
                    k2 = k1;
                    if (key < k0) { k1 = k0; k0 = key; } else k1 = key;
                } else k2 = key;
            } else k3 = key;
        }
    }

    // warp-level pop-4 merge; lane t captures t-th smallest of this warp
    unsigned long long my = ~0ULL;
#pragma unroll
    for (int t = 0; t < 4; ++t) {
        unsigned long long mn = k0;
#pragma unroll
        for (int off = 16; off; off >>= 1) {
            unsigned long long o = __shfl_xor_sync(0xffffffffu, mn, off);
            mn = (o < mn) ? o : mn;
        }
        if (k0 == mn) { k0 = k1; k1 = k2; k2 = k3; k3 = ~0ULL; }
        if (lane == t) my = mn;
    }

    // cross-warp merge: half==1 stashes its 4 into (now dead) vertex smem
    __syncthreads();   // all warps finished reading vertex data
    unsigned long long* buf = (unsigned long long*)sx;
    if (half == 1 && lane < 4) buf[q * 4 + lane] = my;
    __syncthreads();
    if (half == 0 && lane < 8) {
        unsigned long long val = (lane < 4) ? my : buf[q * 4 + (lane - 4)];
        int rank = 0;
#pragma unroll
        for (int j = 0; j < 8; ++j) {
            unsigned long long o = __shfl_sync(0xFFu, val, j, 8);
            rank += (o < val);   // keys unique (index embedded) -> unique ranks
        }
        if (rank < 4)
            g_nbr[(b * NS + s) * KNBR + rank] = (int)(unsigned)val;
    }
}

// -------- cp.async helper --------
__device__ __forceinline__ void cp_async16(void* dst, const void* src)
{
    unsigned d = (unsigned)__cvta_generic_to_shared(dst);
    asm volatile("cp.async.cg.shared.global [%0], [%1], 16;"
                 :: "r"(d), "l"(src) : "memory");
}

// -------- pool gather over one staged plane --------
__device__ __forceinline__ void pool_gather(const float* __restrict__ sf,
                                            int pl, float* __restrict__ out)
{
    int b = pl >> 7, c = pl & 127;
    float* fout = out + BATCH * NS * 3;  // feature_map_pool region
    for (int t = threadIdx.x; t < NS; t += 256) {
        int4 nb = *(const int4*)&g_nbr[(b * NS + t) * KNBR];
        int j0 = nb.x * 3, j1 = nb.y * 3, j2 = nb.z * 3, j3 = nb.w * 3;
        float o0 = fmaxf(fmaxf(sf[j0],     sf[j1]),     fmaxf(sf[j2],     sf[j3]));
        float o1 = fmaxf(fmaxf(sf[j0 + 1], sf[j1 + 1]), fmaxf(sf[j2 + 1], sf[j3 + 1]));
        float o2 = fmaxf(fmaxf(sf[j0 + 2], sf[j1 + 2]), fmaxf(sf[j2 + 2], sf[j3 + 2]));
        size_t ob = ((size_t)(b * NC + c) * NS + t) * 3;
        fout[ob] = o0; fout[ob + 1] = o1; fout[ob + 2] = o2;
    }
}

// -------- K_pool: 2 planes per block, cp.async double-buffered --------------
// grid = 256 blocks, block = 256, dynamic smem = 2 * 48KB
__global__ __launch_bounds__(256) void pool_kernel(const float* __restrict__ F,
                                                   const float* __restrict__ Vtx,
                                                   float* __restrict__ out,
                                                   Samp smp)
{
    extern __shared__ __align__(16) float sf[];
    int pl0 = blockIdx.x * 2;
    const float4* src0 = (const float4*)(F + (size_t)pl0 * PLF);
    const float4* src1 = src0 + PLF / 4;
    float4* d0 = (float4*)sf;
    float4* d1 = d0 + PLF / 4;

    for (int i = threadIdx.x; i < PLF / 4; i += 256) cp_async16(d0 + i, src0 + i);
    asm volatile("cp.async.commit_group;" ::: "memory");
    for (int i = threadIdx.x; i < PLF / 4; i += 256) cp_async16(d1 + i, src1 + i);
    asm volatile("cp.async.commit_group;" ::: "memory");

    asm volatile("cp.async.wait_group 1;" ::: "memory");
    __syncthreads();
    pool_gather(sf, pl0, out);

    asm volatile("cp.async.wait_group 0;" ::: "memory");
    __syncthreads();
    pool_gather(sf + PLF, pl0 + 1, out);

    // blocks owning plane c==0 also emit vertices_pool (b,1024,3)
    if ((pl0 & 127) == 0) {
        int b = pl0 >> 7;
        const float* vb = Vtx + b * NV * 3;
        for (int t = threadIdx.x; t < NS * 3; t += 256) {
            int s = t / 3, d = t - 3 * s;
            out[(b * NS + s) * 3 + d] = vb[smp.s[s] * 3 + d];
        }
    }
}

// -------- host entry --------
extern "C" void kernel_launch(void* const* d_in, const int* in_sizes, int n_in,
                              void* d_out, int out_size)
{
    const float* Vtx;
    const float* F;
    if (in_sizes[0] == BATCH * NV * 3) {
        Vtx = (const float*)d_in[0];
        F   = (const float*)d_in[1];
    } else {
        Vtx = (const float*)d_in[1];
        F   = (const float*)d_in[0];
    }

    // ---- host-side permutation (pure arithmetic; runs at capture time only) ----
    // jax.random.key(42), two partitionable/foldlike splits:
    //   split(k): keys[i] = cipher(k; 0, i); carry = cipher(k;0,0), sub = cipher(k;0,1)
    // random_bits(sub,32,(n,)) partitionable: bits[i] = w0^w1 of cipher(sub; 0, i)
    uint32_t k10, k11, sub_lo[2], sub_hi[2], t0, t1;
    threefry2x32(0u, 42u, 0u, 0u, &k10, &k11);            // round-1 carry key
    threefry2x32(0u, 42u, 0u, 1u, &sub_lo[0], &sub_hi[0]); // round-1 subkey
    threefry2x32(k10, k11, 0u, 1u, &sub_lo[1], &sub_hi[1]);// round-2 subkey
    (void)t0; (void)t1;

    static unsigned long long pk[NV];
    static int rk[2][NV];
    for (int r = 0; r < 2; ++r) {
        for (int i = 0; i < NV; ++i) {
            uint32_t w0, w1;
            threefry2x32(sub_lo[r], sub_hi[r], 0u, (uint32_t)i, &w0, &w1);
            pk[i] = ((unsigned long long)(w0 ^ w1) << 32) | (uint32_t)i;
        }
        std::sort(pk, pk + NV);   // index in low bits -> stable rank
        for (int j = 0; j < NV; ++j) rk[r][(uint32_t)pk[j]] = j;
    }
    static Samp h_samp;
    for (int i = 0; i < NV; ++i) {
        int pos = rk[1][rk[0][i]];
        if (pos < NS) h_samp.s[pos] = i;
    }

    cudaFuncSetAttribute(pool_kernel,
                         cudaFuncAttributeMaxDynamicSharedMemorySize,
                         2 * PLF * (int)sizeof(float));

    knn_kernel<<<BATCH * 128, 512>>>(Vtx, h_samp);
    pool_kernel<<<256, 256, 2 * PLF * sizeof(float)>>>(F, Vtx, (float*)d_out, h_samp);
}